// round 9
// baseline (speedup 1.0000x reference)
#include <cuda_runtime.h>
#include <cstdint>

// Problem constants
#define T_TOK 8192
#define D_DIM 768
#define E_EXP 8
#define F_DIM 3072

// ---------------- device scratch (no allocations allowed) ----------------
__device__ int g_idx[T_TOK];
__device__ int g_cnt[E_EXP];
__device__ int g_off[E_EXP + 1];
__device__ int g_cur[E_EXP];
__device__ int g_perm[T_TOK];
__device__ float g_H[(size_t)T_TOK * F_DIM];   // grouped intermediate rows

// ---------------- helpers ----------------
__device__ __forceinline__ uint32_t pack_f16x2(float lo, float hi) {
    uint32_t r;
    asm("cvt.rn.f16x2.f32 %0, %1, %2;" : "=r"(r) : "f"(hi), "f"(lo));
    return r;
}

__device__ __forceinline__ float gelu_exact(float v) {
    return 0.5f * v * (1.0f + erff(v * 0.70710678118654752f));
}

__device__ __forceinline__ uint32_t smem_u32(const void* p) {
    uint32_t a;
    asm("{ .reg .u64 t; cvta.to.shared.u64 t, %1; cvt.u32.u64 %0, t; }"
        : "=r"(a) : "l"(p));
    return a;
}

__device__ __forceinline__ void cp_async16(uint32_t dst, const void* src) {
    asm volatile("cp.async.cg.shared.global [%0], [%1], 16;"
                 :: "r"(dst), "l"(src) : "memory");
}
#define CP_COMMIT()  asm volatile("cp.async.commit_group;" ::: "memory")
#define CP_WAIT1()   asm volatile("cp.async.wait_group 1;" ::: "memory")

// ---------------- small kernels: routing ----------------
__global__ void zero_kernel() {
    int t = threadIdx.x;
    if (t < E_EXP) { g_cnt[t] = 0; g_cur[t] = 0; }
}

__global__ void gate_kernel(const float* __restrict__ x,
                            const float* __restrict__ gw,
                            const float* __restrict__ gb) {
    int t = blockIdx.x * 8 + (threadIdx.x >> 5);
    int lane = threadIdx.x & 31;
    const float* xr = x + (size_t)t * D_DIM;
    float acc[8] = {0.f,0.f,0.f,0.f,0.f,0.f,0.f,0.f};
    for (int j = lane; j < D_DIM; j += 32) {
        float xv = xr[j];
        const float4* g4 = reinterpret_cast<const float4*>(gw + (size_t)j * 8);
        float4 a = g4[0], b = g4[1];
        acc[0] += xv * a.x; acc[1] += xv * a.y; acc[2] += xv * a.z; acc[3] += xv * a.w;
        acc[4] += xv * b.x; acc[5] += xv * b.y; acc[6] += xv * b.z; acc[7] += xv * b.w;
    }
#pragma unroll
    for (int o = 16; o; o >>= 1)
#pragma unroll
        for (int e = 0; e < 8; e++)
            acc[e] += __shfl_xor_sync(0xffffffffu, acc[e], o);
    if (lane == 0) {
        int best = 0;
        float bv = acc[0] + gb[0];
#pragma unroll
        for (int e = 1; e < 8; e++) {
            float v = acc[e] + gb[e];
            if (v > bv) { bv = v; best = e; }
        }
        g_idx[t] = best;
        atomicAdd(&g_cnt[best], 1);
    }
}

__global__ void offset_kernel() {
    if (threadIdx.x == 0) {
        int s = 0;
        for (int i = 0; i < E_EXP; i++) { g_off[i] = s; s += g_cnt[i]; }
        g_off[E_EXP] = s;
    }
}

__global__ void scatter_kernel() {
    int t = blockIdx.x * 256 + threadIdx.x;
    int e = g_idx[t];
    int p = atomicAdd(&g_cur[e], 1);
    g_perm[g_off[e] + p] = t;
}

// ---------------- grouped GEMM, fp16 mma.sync(m16n8k16), cp.async pipeline --
// dynamic smem layout (floats):
//   stage s (s=0,1) at s*9344:
//     A: 128 rows x stride 40  (5120 floats)   raw f32
//     B: 32 rows  x stride 132 (4224 floats)   raw f32, at +5120
//   sP: int[128] at float-offset 18688
#define STG_F    9344
#define A_STRIDE 40
#define B_STRIDE 132
#define B_BASE   5120
#define SP_OFF   18688
#define SMEM_BYTES 75264

template<int K, int N, bool GATHER_A, bool DO_GELU, bool SCATTER_C>
__global__ void __launch_bounds__(256)
moe_gemm(const float* __restrict__ Ax,
         const float* __restrict__ W,
         const float* __restrict__ Bias,
         float* __restrict__ Cx) {
    extern __shared__ float smf[];
    uint32_t sb = smem_u32(smf);
    int tid = threadIdx.x;

    // map blockIdx.y -> (expert, local m-tile)
    int rt = blockIdx.y;
    int e = -1, mt = 0;
    {
        int base = 0;
#pragma unroll
        for (int i = 0; i < E_EXP; i++) {
            int c = g_off[i + 1] - g_off[i];
            int tl = (c + 127) >> 7;
            if (e < 0 && rt < base + tl) { e = i; mt = rt - base; }
            base += tl;
        }
    }
    if (e < 0) return;

    int cnt   = g_off[e + 1] - g_off[e];
    int m0    = mt << 7;
    int rows  = min(128, cnt - m0);
    int grow0 = g_off[e] + m0;
    int n0    = blockIdx.x << 7;

    int* sP = reinterpret_cast<int*>(smf + SP_OFF);
    if (tid < 128) sP[tid] = (tid < rows) ? g_perm[grow0 + tid] : -1;
    __syncthreads();

    const float* A  = GATHER_A ? Ax : (const float*)g_H;
    const float* We = W + (size_t)e * K * N;

    // per-thread cp.async coordinates
    int a_row = tid >> 3;                 // base row; +i*32 for i=0..3 -> 128 rows
    int a_c4  = (tid & 7) << 2;           // f32 col of 16B chunk (0,4,..,28)
    int b_row = tid >> 5;                 // +i*8 -> 32 rows
    int b_c4  = (tid & 31) << 2;          // f32 col (0,4,..,124)

    // A source row pointers (fixed across k-tiles): 4 rows per thread.
    // Invalid/padded rows CLAMP to a valid row; their accumulators hold
    // garbage but are never stored (rvalid mask in epilogue).
    const float* a_src[4];
#pragma unroll
    for (int i = 0; i < 4; i++) {
        int r = a_row + i * 32;
        if (GATHER_A) {
            int sr = sP[r];
            if (sr < 0) sr = sP[0];
            a_src[i] = A + (size_t)sr * K;
        } else {
            int rr = (r < rows) ? (grow0 + r) : grow0;
            a_src[i] = A + (size_t)rr * K;
        }
    }

    const int NK = K / 32;

    // issue loads for k-tile kt into stage s
    auto issue = [&](int s, int kt) {
        int kbase = kt << 5;
        uint32_t stg = sb + (uint32_t)(s * STG_F * 4);
#pragma unroll
        for (int i = 0; i < 4; i++) {
            int r = a_row + i * 32;
            cp_async16(stg + (uint32_t)((r * A_STRIDE + a_c4) * 4),
                       a_src[i] + kbase + a_c4);
        }
#pragma unroll
        for (int i = 0; i < 4; i++) {
            int r = b_row + i * 8;
            cp_async16(stg + (uint32_t)(B_BASE * 4 + (r * B_STRIDE + b_c4) * 4),
                       We + (size_t)(kbase + r) * N + n0 + b_c4);
        }
    };

    float acc[2][8][4];
#pragma unroll
    for (int im = 0; im < 2; im++)
#pragma unroll
        for (int jn = 0; jn < 8; jn++)
#pragma unroll
            for (int q = 0; q < 4; q++) acc[im][jn][q] = 0.f;

    int wid = tid >> 5, lane = tid & 31;
    int wm = wid & 3, wn = wid >> 2;      // warp tile: 32 rows x 64 cols
    int lr = lane >> 2, lc = lane & 3;

    // prologue: fill both stages
    issue(0, 0); CP_COMMIT();
    issue(1, 1); CP_COMMIT();

    for (int kt = 0; kt < NK; kt++) {
        int s = kt & 1;
        const float* As = smf + s * STG_F;
        const float* Bs = As + B_BASE;

        CP_WAIT1();
        __syncthreads();

        // two k16 steps per 32-wide k-tile
#pragma unroll
        for (int ks2 = 0; ks2 < 2; ks2++) {
            int kk = ks2 * 16 + 2 * lc;
            uint32_t a[2][4], b[8][2];
#pragma unroll
            for (int im = 0; im < 2; im++) {
                int r = wm * 32 + im * 16 + lr;
                float2 p0 = *reinterpret_cast<const float2*>(As + r * A_STRIDE + kk);
                float2 p1 = *reinterpret_cast<const float2*>(As + (r + 8) * A_STRIDE + kk);
                float2 p2 = *reinterpret_cast<const float2*>(As + r * A_STRIDE + kk + 8);
                float2 p3 = *reinterpret_cast<const float2*>(As + (r + 8) * A_STRIDE + kk + 8);
                a[im][0] = pack_f16x2(p0.x, p0.y);
                a[im][1] = pack_f16x2(p1.x, p1.y);
                a[im][2] = pack_f16x2(p2.x, p2.y);
                a[im][3] = pack_f16x2(p3.x, p3.y);
            }
#pragma unroll
            for (int jn = 0; jn < 8; jn++) {
                int n = wn * 64 + jn * 8 + lr;
                float q0 = Bs[kk * B_STRIDE + n];
                float q1 = Bs[(kk + 1) * B_STRIDE + n];
                float q2 = Bs[(kk + 8) * B_STRIDE + n];
                float q3 = Bs[(kk + 9) * B_STRIDE + n];
                b[jn][0] = pack_f16x2(q0, q1);
                b[jn][1] = pack_f16x2(q2, q3);
            }
#pragma unroll
            for (int im = 0; im < 2; im++)
#pragma unroll
                for (int jn = 0; jn < 8; jn++) {
                    asm volatile(
                        "mma.sync.aligned.m16n8k16.row.col.f32.f16.f16.f32 "
                        "{%0,%1,%2,%3}, {%4,%5,%6,%7}, {%8,%9}, {%0,%1,%2,%3};\n"
                        : "+f"(acc[im][jn][0]), "+f"(acc[im][jn][1]),
                          "+f"(acc[im][jn][2]), "+f"(acc[im][jn][3])
                        : "r"(a[im][0]), "r"(a[im][1]), "r"(a[im][2]), "r"(a[im][3]),
                          "r"(b[jn][0]), "r"(b[jn][1]));
                }
        }
        __syncthreads();

        if (kt + 2 < NK) issue(s, kt + 2);
        CP_COMMIT();
    }

    // epilogue
    const float* be = Bias + (size_t)e * N + n0;
#pragma unroll
    for (int im = 0; im < 2; im++) {
#pragma unroll
        for (int half = 0; half < 2; half++) {
            int r = wm * 32 + im * 16 + lr + half * 8;
            bool rvalid = (r < rows);
            int tok = -1;
            if (SCATTER_C && rvalid) tok = sP[r];
#pragma unroll
            for (int jn = 0; jn < 8; jn++) {
                int col = wn * 64 + jn * 8 + lc * 2;
                float v0 = acc[im][jn][half * 2 + 0] + be[col];
                float v1 = acc[im][jn][half * 2 + 1] + be[col + 1];
                if (DO_GELU) { v0 = gelu_exact(v0); v1 = gelu_exact(v1); }
                if (rvalid) {
                    if (SCATTER_C) {
                        float2* dst = reinterpret_cast<float2*>(
                            Cx + (size_t)tok * N + n0 + col);
                        *dst = make_float2(v0, v1);
                    } else {
                        float2* dst = reinterpret_cast<float2*>(
                            g_H + (size_t)(grow0 + r) * N + n0 + col);
                        *dst = make_float2(v0, v1);
                    }
                }
            }
        }
    }
}

// ---------------- launch ----------------
extern "C" void kernel_launch(void* const* d_in, const int* in_sizes, int n_in,
                              void* d_out, int out_size) {
    const float* x  = (const float*)d_in[0];
    const float* gw = (const float*)d_in[1];
    const float* gb = (const float*)d_in[2];
    const float* w1 = (const float*)d_in[3];
    const float* b1 = (const float*)d_in[4];
    const float* w2 = (const float*)d_in[5];
    const float* b2 = (const float*)d_in[6];
    float* out = (float*)d_out;

    cudaFuncSetAttribute(moe_gemm<D_DIM, F_DIM, true,  true,  false>,
                         cudaFuncAttributeMaxDynamicSharedMemorySize, SMEM_BYTES);
    cudaFuncSetAttribute(moe_gemm<F_DIM, D_DIM, false, false, true>,
                         cudaFuncAttributeMaxDynamicSharedMemorySize, SMEM_BYTES);

    zero_kernel<<<1, 32>>>();
    gate_kernel<<<T_TOK / 8, 256>>>(x, gw, gb);
    offset_kernel<<<1, 1>>>();
    scatter_kernel<<<T_TOK / 256, 256>>>();

    // max row tiles across experts: floor(8192/128) + 8 = 72
    moe_gemm<D_DIM, F_DIM, true,  true,  false>
        <<<dim3(F_DIM / 128, 72), 256, SMEM_BYTES>>>(x, w1, b1, nullptr);
    moe_gemm<F_DIM, D_DIM, false, false, true>
        <<<dim3(D_DIM / 128, 72), 256, SMEM_BYTES>>>(nullptr, w2, b2, out);
}

// round 10
// speedup vs baseline: 1.2727x; 1.2727x over previous
#include <cuda_runtime.h>
#include <cstdint>

// Problem constants
#define T_TOK 8192
#define D_DIM 768
#define E_EXP 8
#define F_DIM 3072

// ---------------- device scratch (no allocations allowed) ----------------
__device__ int g_idx[T_TOK];
__device__ int g_cnt[E_EXP];
__device__ int g_off[E_EXP + 1];
__device__ int g_cur[E_EXP];
__device__ int g_perm[T_TOK];
__device__ float g_H[(size_t)T_TOK * F_DIM];   // grouped intermediate rows (tf32-rounded)

// ---------------- helpers ----------------
__device__ __forceinline__ uint32_t f2tf32(float v) {
    uint32_t r;
    asm("cvt.rna.tf32.f32 %0, %1;" : "=r"(r) : "f"(v));
    return r;
}

__device__ __forceinline__ float gelu_exact(float v) {
    return 0.5f * v * (1.0f + erff(v * 0.70710678118654752f));
}

__device__ __forceinline__ uint32_t smem_u32(const void* p) {
    uint32_t a;
    asm("{ .reg .u64 t; cvta.to.shared.u64 t, %1; cvt.u32.u64 %0, t; }"
        : "=r"(a) : "l"(p));
    return a;
}

__device__ __forceinline__ void cp_async16(uint32_t dst, const void* src) {
    asm volatile("cp.async.cg.shared.global [%0], [%1], 16;"
                 :: "r"(dst), "l"(src) : "memory");
}
#define CP_COMMIT()  asm volatile("cp.async.commit_group;" ::: "memory")
#define CP_WAIT1()   asm volatile("cp.async.wait_group 1;" ::: "memory")

// ---------------- small kernels: routing ----------------
__global__ void zero_kernel() {
    int t = threadIdx.x;
    if (t < E_EXP) { g_cnt[t] = 0; g_cur[t] = 0; }
}

__global__ void gate_kernel(const float* __restrict__ x,
                            const float* __restrict__ gw,
                            const float* __restrict__ gb) {
    int t = blockIdx.x * 8 + (threadIdx.x >> 5);
    int lane = threadIdx.x & 31;
    const float* xr = x + (size_t)t * D_DIM;
    float acc[8] = {0.f,0.f,0.f,0.f,0.f,0.f,0.f,0.f};
    for (int j = lane; j < D_DIM; j += 32) {
        float xv = xr[j];
        const float4* g4 = reinterpret_cast<const float4*>(gw + (size_t)j * 8);
        float4 a = g4[0], b = g4[1];
        acc[0] += xv * a.x; acc[1] += xv * a.y; acc[2] += xv * a.z; acc[3] += xv * a.w;
        acc[4] += xv * b.x; acc[5] += xv * b.y; acc[6] += xv * b.z; acc[7] += xv * b.w;
    }
#pragma unroll
    for (int o = 16; o; o >>= 1)
#pragma unroll
        for (int e = 0; e < 8; e++)
            acc[e] += __shfl_xor_sync(0xffffffffu, acc[e], o);
    if (lane == 0) {
        int best = 0;
        float bv = acc[0] + gb[0];
#pragma unroll
        for (int e = 1; e < 8; e++) {
            float v = acc[e] + gb[e];
            if (v > bv) { bv = v; best = e; }
        }
        g_idx[t] = best;
        atomicAdd(&g_cnt[best], 1);
    }
}

__global__ void offset_kernel() {
    if (threadIdx.x == 0) {
        int s = 0;
        for (int i = 0; i < E_EXP; i++) { g_off[i] = s; s += g_cnt[i]; }
        g_off[E_EXP] = s;
    }
}

__global__ void scatter_kernel() {
    int t = blockIdx.x * 256 + threadIdx.x;
    int e = g_idx[t];
    int p = atomicAdd(&g_cur[e], 1);
    g_perm[g_off[e] + p] = t;
}

// ---------------- grouped GEMM, tf32 mma.sync, cp.async 2-stage pipeline ----
// dynamic smem layout (floats):
//   stage s (s=0,1) at s*8960:
//     A: 128 rows x stride 36  (4608 floats)   raw f32
//     B: 32 rows  x stride 136 (4352 floats)   raw f32, at +4608
//   sP: int[128] at float-offset 17920
#define STG_F   8960
#define A_STRIDE 36
#define B_STRIDE 136
#define B_BASE  4608
#define SP_OFF  17920
#define SMEM_BYTES 73728

template<int K, int N, bool GATHER_A, bool DO_GELU, bool SCATTER_C>
__global__ void __launch_bounds__(256, 2)
moe_gemm(const float* __restrict__ Ax,
         const float* __restrict__ W,
         const float* __restrict__ Bias,
         float* __restrict__ Cx) {
    extern __shared__ float smf[];
    uint32_t sb = smem_u32(smf);
    int tid = threadIdx.x;

    // map blockIdx.y -> (expert, local m-tile)
    int rt = blockIdx.y;
    int e = -1, mt = 0;
    {
        int base = 0;
#pragma unroll
        for (int i = 0; i < E_EXP; i++) {
            int c = g_off[i + 1] - g_off[i];
            int tl = (c + 127) >> 7;
            if (e < 0 && rt < base + tl) { e = i; mt = rt - base; }
            base += tl;
        }
    }
    if (e < 0) return;

    int cnt   = g_off[e + 1] - g_off[e];
    int m0    = mt << 7;
    int rows  = min(128, cnt - m0);
    int grow0 = g_off[e] + m0;
    int n0    = blockIdx.x << 7;

    int* sP = reinterpret_cast<int*>(smf + SP_OFF);
    if (tid < 128) sP[tid] = (tid < rows) ? g_perm[grow0 + tid] : -1;
    __syncthreads();

    const float* A  = GATHER_A ? Ax : (const float*)g_H;
    const float* We = W + (size_t)e * K * N;

    // per-thread cp.async coordinates
    int a_row = tid >> 3;                 // base row; +i*32 for i=0..3 -> 128 rows
    int a_c4  = (tid & 7) << 2;           // f32 col of 16B chunk (0,4,..,28)
    int b_row = tid >> 5;                 // +i*8 -> 32 rows
    int b_c4  = (tid & 31) << 2;          // f32 col (0,4,..,124)

    // A source row pointers (fixed across k-tiles): 4 rows per thread.
    // Invalid/padded rows CLAMP to a valid row; their accumulators hold
    // garbage but are never stored (rvalid mask in epilogue).
    const float* a_src[4];
#pragma unroll
    for (int i = 0; i < 4; i++) {
        int r = a_row + i * 32;
        if (GATHER_A) {
            int sr = sP[r];
            if (sr < 0) sr = sP[0];
            a_src[i] = A + (size_t)sr * K;
        } else {
            int rr = (r < rows) ? (grow0 + r) : grow0;
            a_src[i] = A + (size_t)rr * K;
        }
    }

    const int NK = K / 32;

    // issue loads for k-tile kt into stage s
    auto issue = [&](int s, int kt) {
        int kbase = kt << 5;
        uint32_t stg = sb + (uint32_t)(s * STG_F * 4);
#pragma unroll
        for (int i = 0; i < 4; i++) {
            int r = a_row + i * 32;
            cp_async16(stg + (uint32_t)((r * A_STRIDE + a_c4) * 4),
                       a_src[i] + kbase + a_c4);
        }
#pragma unroll
        for (int i = 0; i < 4; i++) {
            int r = b_row + i * 8;
            cp_async16(stg + (uint32_t)(B_BASE * 4 + (r * B_STRIDE + b_c4) * 4),
                       We + (size_t)(kbase + r) * N + n0 + b_c4);
        }
    };

    float acc[2][8][4];
#pragma unroll
    for (int im = 0; im < 2; im++)
#pragma unroll
        for (int jn = 0; jn < 8; jn++)
#pragma unroll
            for (int q = 0; q < 4; q++) acc[im][jn][q] = 0.f;

    int wid = tid >> 5, lane = tid & 31;
    int wm = wid & 3, wn = wid >> 2;      // warp tile: 32 rows x 64 cols
    int lr = lane >> 2, lc = lane & 3;

    // prologue: fill both stages
    issue(0, 0); CP_COMMIT();
    issue(1, 1); CP_COMMIT();

    for (int kt = 0; kt < NK; kt++) {
        int s = kt & 1;
        const float* As = smf + s * STG_F;
        const float* Bs = As + B_BASE;

        CP_WAIT1();
        __syncthreads();

#pragma unroll
        for (int ks = 0; ks < 4; ks++) {
            uint32_t a[2][4], b[8][2];
#pragma unroll
            for (int im = 0; im < 2; im++) {
                int r = wm * 32 + im * 16 + lr;
                int k = ks * 8 + lc;
                if (GATHER_A) {
                    // raw x rows need rounding to tf32
                    a[im][0] = f2tf32(As[r * A_STRIDE + k]);
                    a[im][1] = f2tf32(As[(r + 8) * A_STRIDE + k]);
                    a[im][2] = f2tf32(As[r * A_STRIDE + k + 4]);
                    a[im][3] = f2tf32(As[(r + 8) * A_STRIDE + k + 4]);
                } else {
                    // g_H already stored tf32-rounded: reinterpret, skip cvt
                    a[im][0] = __float_as_uint(As[r * A_STRIDE + k]);
                    a[im][1] = __float_as_uint(As[(r + 8) * A_STRIDE + k]);
                    a[im][2] = __float_as_uint(As[r * A_STRIDE + k + 4]);
                    a[im][3] = __float_as_uint(As[(r + 8) * A_STRIDE + k + 4]);
                }
            }
#pragma unroll
            for (int jn = 0; jn < 8; jn++) {
                int n = wn * 64 + jn * 8 + lr;
                int k = ks * 8 + lc;
                b[jn][0] = f2tf32(Bs[k * B_STRIDE + n]);
                b[jn][1] = f2tf32(Bs[(k + 4) * B_STRIDE + n]);
            }
#pragma unroll
            for (int im = 0; im < 2; im++)
#pragma unroll
                for (int jn = 0; jn < 8; jn++) {
                    asm volatile(
                        "mma.sync.aligned.m16n8k8.row.col.f32.tf32.tf32.f32 "
                        "{%0,%1,%2,%3}, {%4,%5,%6,%7}, {%8,%9}, {%0,%1,%2,%3};\n"
                        : "+f"(acc[im][jn][0]), "+f"(acc[im][jn][1]),
                          "+f"(acc[im][jn][2]), "+f"(acc[im][jn][3])
                        : "r"(a[im][0]), "r"(a[im][1]), "r"(a[im][2]), "r"(a[im][3]),
                          "r"(b[jn][0]), "r"(b[jn][1]));
                }
        }
        __syncthreads();

        if (kt + 2 < NK) issue(s, kt + 2);
        CP_COMMIT();
    }

    // epilogue
    const float* be = Bias + (size_t)e * N + n0;
#pragma unroll
    for (int im = 0; im < 2; im++) {
#pragma unroll
        for (int half = 0; half < 2; half++) {
            int r = wm * 32 + im * 16 + lr + half * 8;
            bool rvalid = (r < rows);
            int tok = -1;
            if (SCATTER_C && rvalid) tok = sP[r];
#pragma unroll
            for (int jn = 0; jn < 8; jn++) {
                int col = wn * 64 + jn * 8 + lc * 2;
                float v0 = acc[im][jn][half * 2 + 0] + be[col];
                float v1 = acc[im][jn][half * 2 + 1] + be[col + 1];
                if (DO_GELU) { v0 = gelu_exact(v0); v1 = gelu_exact(v1); }
                if (rvalid) {
                    if (SCATTER_C) {
                        float2* dst = reinterpret_cast<float2*>(
                            Cx + (size_t)tok * N + n0 + col);
                        *dst = make_float2(v0, v1);
                    } else {
                        // store tf32-rounded so GEMM2 can skip the cvt
                        float2* dst = reinterpret_cast<float2*>(
                            g_H + (size_t)(grow0 + r) * N + n0 + col);
                        *dst = make_float2(__uint_as_float(f2tf32(v0)),
                                           __uint_as_float(f2tf32(v1)));
                    }
                }
            }
        }
    }
}

// ---------------- launch ----------------
extern "C" void kernel_launch(void* const* d_in, const int* in_sizes, int n_in,
                              void* d_out, int out_size) {
    const float* x  = (const float*)d_in[0];
    const float* gw = (const float*)d_in[1];
    const float* gb = (const float*)d_in[2];
    const float* w1 = (const float*)d_in[3];
    const float* b1 = (const float*)d_in[4];
    const float* w2 = (const float*)d_in[5];
    const float* b2 = (const float*)d_in[6];
    float* out = (float*)d_out;

    cudaFuncSetAttribute(moe_gemm<D_DIM, F_DIM, true,  true,  false>,
                         cudaFuncAttributeMaxDynamicSharedMemorySize, SMEM_BYTES);
    cudaFuncSetAttribute(moe_gemm<F_DIM, D_DIM, false, false, true>,
                         cudaFuncAttributeMaxDynamicSharedMemorySize, SMEM_BYTES);

    zero_kernel<<<1, 32>>>();
    gate_kernel<<<T_TOK / 8, 256>>>(x, gw, gb);
    offset_kernel<<<1, 1>>>();
    scatter_kernel<<<T_TOK / 256, 256>>>();

    // max row tiles across experts: floor(8192/128) + 8 = 72
    moe_gemm<D_DIM, F_DIM, true,  true,  false>
        <<<dim3(F_DIM / 128, 72), 256, SMEM_BYTES>>>(x, w1, b1, nullptr);
    moe_gemm<F_DIM, D_DIM, false, false, true>
        <<<dim3(D_DIM / 128, 72), 256, SMEM_BYTES>>>(nullptr, w2, b2, out);
}

// round 11
// speedup vs baseline: 2.0320x; 1.5966x over previous
#include <cuda_runtime.h>
#include <cuda_fp16.h>
#include <cstdint>

// Problem constants
#define T_TOK 8192
#define D_DIM 768
#define E_EXP 8
#define F_DIM 3072

// ---------------- device scratch (no allocations allowed) ----------------
__device__ int g_idx[T_TOK];
__device__ int g_cnt[E_EXP];
__device__ int g_off[E_EXP + 1];
__device__ int g_cur[E_EXP];
__device__ int g_perm[T_TOK];
__device__ __half g_xh[(size_t)T_TOK * D_DIM];          // x in f16
__device__ __half g_w1h[(size_t)E_EXP * D_DIM * F_DIM]; // w1 in f16
__device__ __half g_w2h[(size_t)E_EXP * F_DIM * D_DIM]; // w2 in f16
__device__ __half g_Hh[(size_t)T_TOK * F_DIM];          // grouped intermediate, f16

// ---------------- helpers ----------------
__device__ __forceinline__ float gelu_exact(float v) {
    return 0.5f * v * (1.0f + erff(v * 0.70710678118654752f));
}

__device__ __forceinline__ uint32_t smem_u32(const void* p) {
    uint32_t a;
    asm("{ .reg .u64 t; cvta.to.shared.u64 t, %1; cvt.u32.u64 %0, t; }"
        : "=r"(a) : "l"(p));
    return a;
}

__device__ __forceinline__ void cp_async16(uint32_t dst, const void* src) {
    asm volatile("cp.async.cg.shared.global [%0], [%1], 16;"
                 :: "r"(dst), "l"(src) : "memory");
}
#define CP_COMMIT()  asm volatile("cp.async.commit_group;" ::: "memory")
#define CP_WAIT1()   asm volatile("cp.async.wait_group 1;" ::: "memory")

__device__ __forceinline__ void ldsm_x4(uint32_t& r0, uint32_t& r1,
                                        uint32_t& r2, uint32_t& r3, uint32_t addr) {
    asm volatile("ldmatrix.sync.aligned.m8n8.x4.shared.b16 {%0,%1,%2,%3}, [%4];"
                 : "=r"(r0), "=r"(r1), "=r"(r2), "=r"(r3) : "r"(addr));
}
__device__ __forceinline__ void ldsm_x4t(uint32_t& r0, uint32_t& r1,
                                         uint32_t& r2, uint32_t& r3, uint32_t addr) {
    asm volatile("ldmatrix.sync.aligned.m8n8.x4.trans.shared.b16 {%0,%1,%2,%3}, [%4];"
                 : "=r"(r0), "=r"(r1), "=r"(r2), "=r"(r3) : "r"(addr));
}

// ---------------- conversion + routing kernels ----------------
__global__ void convw_kernel(const float* __restrict__ src, __half* __restrict__ dst, int n4) {
    int i = blockIdx.x * 256 + threadIdx.x;
    if (i < n4) {
        float4 v = reinterpret_cast<const float4*>(src)[i];
        __half2* d = reinterpret_cast<__half2*>(dst) + (size_t)i * 2;
        d[0] = __floats2half2_rn(v.x, v.y);
        d[1] = __floats2half2_rn(v.z, v.w);
    }
}

__global__ void zero_kernel() {
    int t = threadIdx.x;
    if (t < E_EXP) { g_cnt[t] = 0; g_cur[t] = 0; }
}

// one warp per token: logits + argmax; also converts the token row to f16
__global__ void gate_kernel(const float* __restrict__ x,
                            const float* __restrict__ gw,
                            const float* __restrict__ gb) {
    int t = blockIdx.x * 8 + (threadIdx.x >> 5);
    int lane = threadIdx.x & 31;
    const float* xr = x + (size_t)t * D_DIM;
    __half* xh = g_xh + (size_t)t * D_DIM;
    float acc[8] = {0.f,0.f,0.f,0.f,0.f,0.f,0.f,0.f};
    for (int j = lane; j < D_DIM; j += 32) {
        float xv = xr[j];
        xh[j] = __float2half_rn(xv);
        const float4* g4 = reinterpret_cast<const float4*>(gw + (size_t)j * 8);
        float4 a = g4[0], b = g4[1];
        acc[0] += xv * a.x; acc[1] += xv * a.y; acc[2] += xv * a.z; acc[3] += xv * a.w;
        acc[4] += xv * b.x; acc[5] += xv * b.y; acc[6] += xv * b.z; acc[7] += xv * b.w;
    }
#pragma unroll
    for (int o = 16; o; o >>= 1)
#pragma unroll
        for (int e = 0; e < 8; e++)
            acc[e] += __shfl_xor_sync(0xffffffffu, acc[e], o);
    if (lane == 0) {
        int best = 0;
        float bv = acc[0] + gb[0];
#pragma unroll
        for (int e = 1; e < 8; e++) {
            float v = acc[e] + gb[e];
            if (v > bv) { bv = v; best = e; }
        }
        g_idx[t] = best;
        atomicAdd(&g_cnt[best], 1);
    }
}

__global__ void offset_kernel() {
    if (threadIdx.x == 0) {
        int s = 0;
        for (int i = 0; i < E_EXP; i++) { g_off[i] = s; s += g_cnt[i]; }
        g_off[E_EXP] = s;
    }
}

__global__ void scatter_kernel() {
    int t = blockIdx.x * 256 + threadIdx.x;
    int e = g_idx[t];
    int p = atomicAdd(&g_cur[e], 1);
    g_perm[g_off[e] + p] = t;
}

// ---------------- grouped GEMM, f16 mma.m16n8k16 + ldmatrix, cp.async x2 ----
// smem bytes per stage: A 128x40 f16 = 10240 ; B 32x136 f16 = 8704 -> 18944
// layout: stage s at s*18944 { A at +0, B at +10240 }, sP int[128] at 37888
#define STG_B   18944
#define B_OFFB  10240
#define SP_OFFB 37888
#define SMEM_BYTES 38400

template<int K, int N, bool GATHER_A, bool DO_GELU, bool SCATTER_C>
__global__ void __launch_bounds__(256, 2)
moe_gemm(const __half* __restrict__ Ah,
         const __half* __restrict__ Wh,
         const float* __restrict__ Bias,
         float* __restrict__ Cx) {
    extern __shared__ char smc[];
    uint32_t sb = smem_u32(smc);
    int tid = threadIdx.x;

    // map blockIdx.y -> (expert, local m-tile)
    int rt = blockIdx.y;
    int e = -1, mt = 0;
    {
        int base = 0;
#pragma unroll
        for (int i = 0; i < E_EXP; i++) {
            int c = g_off[i + 1] - g_off[i];
            int tl = (c + 127) >> 7;
            if (e < 0 && rt < base + tl) { e = i; mt = rt - base; }
            base += tl;
        }
    }
    if (e < 0) return;

    int cnt   = g_off[e + 1] - g_off[e];
    int m0    = mt << 7;
    int rows  = min(128, cnt - m0);
    int grow0 = g_off[e] + m0;
    int n0    = blockIdx.x << 7;

    int* sP = reinterpret_cast<int*>(smc + SP_OFFB);
    if (tid < 128) sP[tid] = (tid < rows) ? g_perm[grow0 + tid] : -1;
    __syncthreads();

    const __half* We = Wh + (size_t)e * K * N;

    // cp.async coordinates (f16: 16B = 8 halves)
    int a_row = tid >> 2;                 // +i*64 -> 128 rows
    int a_c8  = (tid & 3) << 3;           // f16 col (0,8,16,24)
    int b_row = tid >> 4;                 // +i*16 -> 32 rows
    int b_c8  = (tid & 15) << 3;          // f16 col (0..120)

    // A source row pointers; invalid rows clamp to a valid row (their
    // accumulators are garbage but masked off in the epilogue)
    const __half* a_src[2];
#pragma unroll
    for (int i = 0; i < 2; i++) {
        int r = a_row + i * 64;
        if (GATHER_A) {
            int sr = sP[r];
            if (sr < 0) sr = sP[0];
            a_src[i] = Ah + (size_t)sr * K;
        } else {
            int rr = (r < rows) ? (grow0 + r) : grow0;
            a_src[i] = Ah + (size_t)rr * K;
        }
    }

    const int NK = K / 32;

    auto issue = [&](int s, int kt) {
        int kbase = kt << 5;
        uint32_t stg = sb + (uint32_t)(s * STG_B);
#pragma unroll
        for (int i = 0; i < 2; i++) {
            int r = a_row + i * 64;
            cp_async16(stg + (uint32_t)((r * 40 + a_c8) * 2),
                       a_src[i] + kbase + a_c8);
        }
#pragma unroll
        for (int i = 0; i < 2; i++) {
            int r = b_row + i * 16;
            cp_async16(stg + B_OFFB + (uint32_t)((r * 136 + b_c8) * 2),
                       We + (size_t)(kbase + r) * N + n0 + b_c8);
        }
    };

    float acc[2][8][4];
#pragma unroll
    for (int im = 0; im < 2; im++)
#pragma unroll
        for (int jn = 0; jn < 8; jn++)
#pragma unroll
            for (int q = 0; q < 4; q++) acc[im][jn][q] = 0.f;

    int wid = tid >> 5, lane = tid & 31;
    int wm = wid & 3, wn = wid >> 2;      // warp tile: 32 rows x 64 cols
    int lr = lane >> 2, lc = lane & 3;

    // ldmatrix lane offsets (bytes)
    uint32_t a_lo = (uint32_t)((((lane & 15) * 40) + ((lane & 16) >> 1)) * 2);
    uint32_t b_lo = (uint32_t)(((((lane & 7) + (lane & 8)) * 136) + ((lane & 16) >> 1)) * 2);

    issue(0, 0); CP_COMMIT();
    issue(1, 1); CP_COMMIT();

    for (int kt = 0; kt < NK; kt++) {
        int s = kt & 1;
        uint32_t stg = sb + (uint32_t)(s * STG_B);

        CP_WAIT1();
        __syncthreads();

#pragma unroll
        for (int step = 0; step < 2; step++) {
            int kk = step << 4;
            uint32_t a[2][4], b[8][2];
#pragma unroll
            for (int im = 0; im < 2; im++) {
                uint32_t addr = stg + (uint32_t)(((wm * 32 + im * 16) * 40 + kk) * 2) + a_lo;
                ldsm_x4(a[im][0], a[im][1], a[im][2], a[im][3], addr);
            }
#pragma unroll
            for (int jn2 = 0; jn2 < 4; jn2++) {
                uint32_t addr = stg + B_OFFB
                              + (uint32_t)((kk * 136 + wn * 64 + jn2 * 16) * 2) + b_lo;
                ldsm_x4t(b[jn2 * 2][0], b[jn2 * 2][1],
                         b[jn2 * 2 + 1][0], b[jn2 * 2 + 1][1], addr);
            }
#pragma unroll
            for (int im = 0; im < 2; im++)
#pragma unroll
                for (int jn = 0; jn < 8; jn++) {
                    asm volatile(
                        "mma.sync.aligned.m16n8k16.row.col.f32.f16.f16.f32 "
                        "{%0,%1,%2,%3}, {%4,%5,%6,%7}, {%8,%9}, {%0,%1,%2,%3};\n"
                        : "+f"(acc[im][jn][0]), "+f"(acc[im][jn][1]),
                          "+f"(acc[im][jn][2]), "+f"(acc[im][jn][3])
                        : "r"(a[im][0]), "r"(a[im][1]), "r"(a[im][2]), "r"(a[im][3]),
                          "r"(b[jn][0]), "r"(b[jn][1]));
                }
        }
        __syncthreads();

        if (kt + 2 < NK) issue(s, kt + 2);
        CP_COMMIT();
    }

    // epilogue
    const float* be = Bias + (size_t)e * N + n0;
#pragma unroll
    for (int im = 0; im < 2; im++) {
#pragma unroll
        for (int half = 0; half < 2; half++) {
            int r = wm * 32 + im * 16 + lr + half * 8;
            bool rvalid = (r < rows);
            int tok = -1;
            if (SCATTER_C && rvalid) tok = sP[r];
#pragma unroll
            for (int jn = 0; jn < 8; jn++) {
                int col = wn * 64 + jn * 8 + lc * 2;
                float v0 = acc[im][jn][half * 2 + 0] + be[col];
                float v1 = acc[im][jn][half * 2 + 1] + be[col + 1];
                if (DO_GELU) { v0 = gelu_exact(v0); v1 = gelu_exact(v1); }
                if (rvalid) {
                    if (SCATTER_C) {
                        float2* dst = reinterpret_cast<float2*>(
                            Cx + (size_t)tok * N + n0 + col);
                        *dst = make_float2(v0, v1);
                    } else {
                        __half2* dst = reinterpret_cast<__half2*>(
                            g_Hh + (size_t)(grow0 + r) * N + n0 + col);
                        *dst = __floats2half2_rn(v0, v1);
                    }
                }
            }
        }
    }
}

// ---------------- launch ----------------
extern "C" void kernel_launch(void* const* d_in, const int* in_sizes, int n_in,
                              void* d_out, int out_size) {
    const float* x  = (const float*)d_in[0];
    const float* gw = (const float*)d_in[1];
    const float* gb = (const float*)d_in[2];
    const float* w1 = (const float*)d_in[3];
    const float* b1 = (const float*)d_in[4];
    const float* w2 = (const float*)d_in[5];
    const float* b2 = (const float*)d_in[6];
    float* out = (float*)d_out;

    __half* w1h; cudaGetSymbolAddress((void**)&w1h, g_w1h);
    __half* w2h; cudaGetSymbolAddress((void**)&w2h, g_w2h);
    __half* xh;  cudaGetSymbolAddress((void**)&xh,  g_xh);
    __half* Hh;  cudaGetSymbolAddress((void**)&Hh,  g_Hh);

    cudaFuncSetAttribute(moe_gemm<D_DIM, F_DIM, true,  true,  false>,
                         cudaFuncAttributeMaxDynamicSharedMemorySize, SMEM_BYTES);
    cudaFuncSetAttribute(moe_gemm<F_DIM, D_DIM, false, false, true>,
                         cudaFuncAttributeMaxDynamicSharedMemorySize, SMEM_BYTES);

    const int WN4 = E_EXP * D_DIM * F_DIM / 4;   // 4,718,592
    convw_kernel<<<(WN4 + 255) / 256, 256>>>(w1, w1h, WN4);
    convw_kernel<<<(WN4 + 255) / 256, 256>>>(w2, w2h, WN4);

    zero_kernel<<<1, 32>>>();
    gate_kernel<<<T_TOK / 8, 256>>>(x, gw, gb);
    offset_kernel<<<1, 1>>>();
    scatter_kernel<<<T_TOK / 256, 256>>>();

    // max row tiles across experts: floor(8192/128) + 8 = 72
    moe_gemm<D_DIM, F_DIM, true,  true,  false>
        <<<dim3(F_DIM / 128, 72), 256, SMEM_BYTES>>>(xh, w1h, b1, nullptr);
    moe_gemm<F_DIM, D_DIM, false, false, true>
        <<<dim3(D_DIM / 128, 72), 256, SMEM_BYTES>>>(Hh, w2h, b2, out);
}

// round 12
// speedup vs baseline: 2.0806x; 1.0239x over previous
#include <cuda_runtime.h>
#include <cuda_fp16.h>
#include <cstdint>

// Problem constants
#define T_TOK 8192
#define D_DIM 768
#define E_EXP 8
#define F_DIM 3072

// ---------------- device scratch (no allocations allowed) ----------------
__device__ int g_idx[T_TOK];
__device__ int g_cnt[E_EXP];
__device__ int g_off[E_EXP + 1];
__device__ int g_cur[E_EXP];
__device__ int g_perm[T_TOK];
__device__ __half g_xh[(size_t)T_TOK * D_DIM];          // x in f16
__device__ __half g_w1h[(size_t)E_EXP * D_DIM * F_DIM]; // w1 in f16
__device__ __half g_w2h[(size_t)E_EXP * F_DIM * D_DIM]; // w2 in f16
__device__ __half g_Hh[(size_t)T_TOK * F_DIM];          // grouped intermediate, f16

// ---------------- helpers ----------------
__device__ __forceinline__ float gelu_exact(float v) {
    return 0.5f * v * (1.0f + erff(v * 0.70710678118654752f));
}

__device__ __forceinline__ uint32_t smem_u32(const void* p) {
    uint32_t a;
    asm("{ .reg .u64 t; cvta.to.shared.u64 t, %1; cvt.u32.u64 %0, t; }"
        : "=r"(a) : "l"(p));
    return a;
}

__device__ __forceinline__ void cp_async16(uint32_t dst, const void* src) {
    asm volatile("cp.async.cg.shared.global [%0], [%1], 16;"
                 :: "r"(dst), "l"(src) : "memory");
}
#define CP_COMMIT()  asm volatile("cp.async.commit_group;" ::: "memory")
#define CP_WAIT1()   asm volatile("cp.async.wait_group 1;" ::: "memory")

__device__ __forceinline__ void ldsm_x4(uint32_t& r0, uint32_t& r1,
                                        uint32_t& r2, uint32_t& r3, uint32_t addr) {
    asm volatile("ldmatrix.sync.aligned.m8n8.x4.shared.b16 {%0,%1,%2,%3}, [%4];"
                 : "=r"(r0), "=r"(r1), "=r"(r2), "=r"(r3) : "r"(addr));
}
__device__ __forceinline__ void ldsm_x4t(uint32_t& r0, uint32_t& r1,
                                         uint32_t& r2, uint32_t& r3, uint32_t addr) {
    asm volatile("ldmatrix.sync.aligned.m8n8.x4.trans.shared.b16 {%0,%1,%2,%3}, [%4];"
                 : "=r"(r0), "=r"(r1), "=r"(r2), "=r"(r3) : "r"(addr));
}

// ---------------- conversion + routing kernels ----------------
// also zeroes the routing counters from block 0 (runs before gate_kernel)
__global__ void convw_kernel(const float* __restrict__ src, __half* __restrict__ dst, int n4) {
    if (blockIdx.x == 0 && threadIdx.x < E_EXP) {
        g_cnt[threadIdx.x] = 0;
        g_cur[threadIdx.x] = 0;
    }
    int i = blockIdx.x * 256 + threadIdx.x;
    if (i < n4) {
        float4 v = reinterpret_cast<const float4*>(src)[i];
        __half2* d = reinterpret_cast<__half2*>(dst) + (size_t)i * 2;
        d[0] = __floats2half2_rn(v.x, v.y);
        d[1] = __floats2half2_rn(v.z, v.w);
    }
}

// one warp per token: logits + argmax; also converts the token row to f16.
// unrolled x4 so 4 independent LDGs are in flight per iteration.
__global__ void gate_kernel(const float* __restrict__ x,
                            const float* __restrict__ gw,
                            const float* __restrict__ gb) {
    int t = blockIdx.x * 8 + (threadIdx.x >> 5);
    int lane = threadIdx.x & 31;
    const float* xr = x + (size_t)t * D_DIM;
    __half* xh = g_xh + (size_t)t * D_DIM;
    float acc[8] = {0.f,0.f,0.f,0.f,0.f,0.f,0.f,0.f};
#pragma unroll
    for (int jo = 0; jo < D_DIM; jo += 128) {
        float xv[4];
#pragma unroll
        for (int u = 0; u < 4; u++) xv[u] = xr[jo + u * 32 + lane];
#pragma unroll
        for (int u = 0; u < 4; u++) xh[jo + u * 32 + lane] = __float2half_rn(xv[u]);
#pragma unroll
        for (int u = 0; u < 4; u++) {
            const float4* g4 = reinterpret_cast<const float4*>(
                gw + (size_t)(jo + u * 32 + lane) * 8);
            float4 a = g4[0], b = g4[1];
            acc[0] += xv[u] * a.x; acc[1] += xv[u] * a.y;
            acc[2] += xv[u] * a.z; acc[3] += xv[u] * a.w;
            acc[4] += xv[u] * b.x; acc[5] += xv[u] * b.y;
            acc[6] += xv[u] * b.z; acc[7] += xv[u] * b.w;
        }
    }
#pragma unroll
    for (int o = 16; o; o >>= 1)
#pragma unroll
        for (int e = 0; e < 8; e++)
            acc[e] += __shfl_xor_sync(0xffffffffu, acc[e], o);
    if (lane == 0) {
        int best = 0;
        float bv = acc[0] + gb[0];
#pragma unroll
        for (int e = 1; e < 8; e++) {
            float v = acc[e] + gb[e];
            if (v > bv) { bv = v; best = e; }
        }
        g_idx[t] = best;
        atomicAdd(&g_cnt[best], 1);
    }
}

__global__ void offset_kernel() {
    if (threadIdx.x == 0) {
        int s = 0;
        for (int i = 0; i < E_EXP; i++) { g_off[i] = s; s += g_cnt[i]; }
        g_off[E_EXP] = s;
    }
}

__global__ void scatter_kernel() {
    int t = blockIdx.x * 256 + threadIdx.x;
    int e = g_idx[t];
    int p = atomicAdd(&g_cur[e], 1);
    g_perm[g_off[e] + p] = t;
}

// ---------------- grouped GEMM, f16 mma.m16n8k16 + ldmatrix, cp.async x2 ----
// smem bytes per stage: A 128x40 f16 = 10240 ; B 32x136 f16 = 8704 -> 18944
// layout: stage s at s*18944 { A at +0, B at +10240 }, sP int[128] at 37888
#define STG_B   18944
#define B_OFFB  10240
#define SP_OFFB 37888
#define SMEM_BYTES 38400

template<int K, int N, bool GATHER_A, bool DO_GELU, bool SCATTER_C>
__global__ void __launch_bounds__(256, 2)
moe_gemm(const __half* __restrict__ Ah,
         const __half* __restrict__ Wh,
         const float* __restrict__ Bias,
         float* __restrict__ Cx) {
    extern __shared__ char smc[];
    uint32_t sb = smem_u32(smc);
    int tid = threadIdx.x;

    // map blockIdx.y -> (expert, local m-tile)
    int rt = blockIdx.y;
    int e = -1, mt = 0;
    {
        int base = 0;
#pragma unroll
        for (int i = 0; i < E_EXP; i++) {
            int c = g_off[i + 1] - g_off[i];
            int tl = (c + 127) >> 7;
            if (e < 0 && rt < base + tl) { e = i; mt = rt - base; }
            base += tl;
        }
    }
    if (e < 0) return;

    int cnt   = g_off[e + 1] - g_off[e];
    int m0    = mt << 7;
    int rows  = min(128, cnt - m0);
    int grow0 = g_off[e] + m0;
    int n0    = blockIdx.x << 7;

    int* sP = reinterpret_cast<int*>(smc + SP_OFFB);
    if (tid < 128) sP[tid] = (tid < rows) ? g_perm[grow0 + tid] : -1;
    __syncthreads();

    const __half* We = Wh + (size_t)e * K * N;

    // cp.async coordinates (f16: 16B = 8 halves)
    int a_row = tid >> 2;                 // +i*64 -> 128 rows
    int a_c8  = (tid & 3) << 3;           // f16 col (0,8,16,24)
    int b_row = tid >> 4;                 // +i*16 -> 32 rows
    int b_c8  = (tid & 15) << 3;          // f16 col (0..120)

    // A source row pointers; invalid rows clamp to a valid row (their
    // accumulators are garbage but masked off in the epilogue)
    const __half* a_src[2];
#pragma unroll
    for (int i = 0; i < 2; i++) {
        int r = a_row + i * 64;
        if (GATHER_A) {
            int sr = sP[r];
            if (sr < 0) sr = sP[0];
            a_src[i] = Ah + (size_t)sr * K;
        } else {
            int rr = (r < rows) ? (grow0 + r) : grow0;
            a_src[i] = Ah + (size_t)rr * K;
        }
    }

    const int NK = K / 32;

    auto issue = [&](int s, int kt) {
        int kbase = kt << 5;
        uint32_t stg = sb + (uint32_t)(s * STG_B);
#pragma unroll
        for (int i = 0; i < 2; i++) {
            int r = a_row + i * 64;
            cp_async16(stg + (uint32_t)((r * 40 + a_c8) * 2),
                       a_src[i] + kbase + a_c8);
        }
#pragma unroll
        for (int i = 0; i < 2; i++) {
            int r = b_row + i * 16;
            cp_async16(stg + B_OFFB + (uint32_t)((r * 136 + b_c8) * 2),
                       We + (size_t)(kbase + r) * N + n0 + b_c8);
        }
    };

    float acc[2][8][4];
#pragma unroll
    for (int im = 0; im < 2; im++)
#pragma unroll
        for (int jn = 0; jn < 8; jn++)
#pragma unroll
            for (int q = 0; q < 4; q++) acc[im][jn][q] = 0.f;

    int wid = tid >> 5, lane = tid & 31;
    int wm = wid & 3, wn = wid >> 2;      // warp tile: 32 rows x 64 cols
    int lr = lane >> 2, lc = lane & 3;

    // ldmatrix lane offsets (bytes)
    uint32_t a_lo = (uint32_t)((((lane & 15) * 40) + ((lane & 16) >> 1)) * 2);
    uint32_t b_lo = (uint32_t)(((((lane & 7) + (lane & 8)) * 136) + ((lane & 16) >> 1)) * 2);

    issue(0, 0); CP_COMMIT();
    issue(1, 1); CP_COMMIT();

    for (int kt = 0; kt < NK; kt++) {
        int s = kt & 1;
        uint32_t stg = sb + (uint32_t)(s * STG_B);

        CP_WAIT1();
        __syncthreads();

#pragma unroll
        for (int step = 0; step < 2; step++) {
            int kk = step << 4;
            uint32_t a[2][4], b[8][2];
#pragma unroll
            for (int im = 0; im < 2; im++) {
                uint32_t addr = stg + (uint32_t)(((wm * 32 + im * 16) * 40 + kk) * 2) + a_lo;
                ldsm_x4(a[im][0], a[im][1], a[im][2], a[im][3], addr);
            }
#pragma unroll
            for (int jn2 = 0; jn2 < 4; jn2++) {
                uint32_t addr = stg + B_OFFB
                              + (uint32_t)((kk * 136 + wn * 64 + jn2 * 16) * 2) + b_lo;
                ldsm_x4t(b[jn2 * 2][0], b[jn2 * 2][1],
                         b[jn2 * 2 + 1][0], b[jn2 * 2 + 1][1], addr);
            }
#pragma unroll
            for (int im = 0; im < 2; im++)
#pragma unroll
                for (int jn = 0; jn < 8; jn++) {
                    asm volatile(
                        "mma.sync.aligned.m16n8k16.row.col.f32.f16.f16.f32 "
                        "{%0,%1,%2,%3}, {%4,%5,%6,%7}, {%8,%9}, {%0,%1,%2,%3};\n"
                        : "+f"(acc[im][jn][0]), "+f"(acc[im][jn][1]),
                          "+f"(acc[im][jn][2]), "+f"(acc[im][jn][3])
                        : "r"(a[im][0]), "r"(a[im][1]), "r"(a[im][2]), "r"(a[im][3]),
                          "r"(b[jn][0]), "r"(b[jn][1]));
                }
        }
        __syncthreads();

        if (kt + 2 < NK) issue(s, kt + 2);
        CP_COMMIT();
    }

    // epilogue
    const float* be = Bias + (size_t)e * N + n0;
#pragma unroll
    for (int im = 0; im < 2; im++) {
#pragma unroll
        for (int half = 0; half < 2; half++) {
            int r = wm * 32 + im * 16 + lr + half * 8;
            bool rvalid = (r < rows);
            int tok = -1;
            if (SCATTER_C && rvalid) tok = sP[r];
#pragma unroll
            for (int jn = 0; jn < 8; jn++) {
                int col = wn * 64 + jn * 8 + lc * 2;
                float v0 = acc[im][jn][half * 2 + 0] + be[col];
                float v1 = acc[im][jn][half * 2 + 1] + be[col + 1];
                if (DO_GELU) { v0 = gelu_exact(v0); v1 = gelu_exact(v1); }
                if (rvalid) {
                    if (SCATTER_C) {
                        float2* dst = reinterpret_cast<float2*>(
                            Cx + (size_t)tok * N + n0 + col);
                        *dst = make_float2(v0, v1);
                    } else {
                        __half2* dst = reinterpret_cast<__half2*>(
                            g_Hh + (size_t)(grow0 + r) * N + n0 + col);
                        *dst = __floats2half2_rn(v0, v1);
                    }
                }
            }
        }
    }
}

// ---------------- launch ----------------
extern "C" void kernel_launch(void* const* d_in, const int* in_sizes, int n_in,
                              void* d_out, int out_size) {
    const float* x  = (const float*)d_in[0];
    const float* gw = (const float*)d_in[1];
    const float* gb = (const float*)d_in[2];
    const float* w1 = (const float*)d_in[3];
    const float* b1 = (const float*)d_in[4];
    const float* w2 = (const float*)d_in[5];
    const float* b2 = (const float*)d_in[6];
    float* out = (float*)d_out;

    __half* w1h; cudaGetSymbolAddress((void**)&w1h, g_w1h);
    __half* w2h; cudaGetSymbolAddress((void**)&w2h, g_w2h);
    __half* xh;  cudaGetSymbolAddress((void**)&xh,  g_xh);
    __half* Hh;  cudaGetSymbolAddress((void**)&Hh,  g_Hh);

    cudaFuncSetAttribute(moe_gemm<D_DIM, F_DIM, true,  true,  false>,
                         cudaFuncAttributeMaxDynamicSharedMemorySize, SMEM_BYTES);
    cudaFuncSetAttribute(moe_gemm<F_DIM, D_DIM, false, false, true>,
                         cudaFuncAttributeMaxDynamicSharedMemorySize, SMEM_BYTES);

    const int WN4 = E_EXP * D_DIM * F_DIM / 4;   // 4,718,592
    convw_kernel<<<(WN4 + 255) / 256, 256>>>(w1, w1h, WN4);   // also zeroes counters
    convw_kernel<<<(WN4 + 255) / 256, 256>>>(w2, w2h, WN4);

    gate_kernel<<<T_TOK / 8, 256>>>(x, gw, gb);
    offset_kernel<<<1, 1>>>();
    scatter_kernel<<<T_TOK / 256, 256>>>();

    // launches 6 & 7 (ncu -s 5 -c 1 lands on gemm1)
    moe_gemm<D_DIM, F_DIM, true,  true,  false>
        <<<dim3(F_DIM / 128, 72), 256, SMEM_BYTES>>>(xh, w1h, b1, nullptr);
    moe_gemm<F_DIM, D_DIM, false, false, true>
        <<<dim3(D_DIM / 128, 72), 256, SMEM_BYTES>>>(Hh, w2h, b2, out);
}